// round 10
// baseline (speedup 1.0000x reference)
#include <cuda_runtime.h>
#include <cuda_fp16.h>
#include <math.h>
#include <stdint.h>

#define NROWS 65536
#define DIMS  64
#define KCODE 1024
#define BM    128
#define THREADS 256
#define NCHUNK 32           // 32 chunks of 32 codes
#define CHW    32
#define NBLK   (NROWS/BM)   // 512 row-blocks
#define GRID   296          // 148 SMs x occ 2; work-stealing

// output layout (floats): [loss(1) | quantized(4194304) | perplexity(1) | encodings(67108864)]
#define Q_OFF    1
#define Q_SIZE   4194304
#define P_OFF    (Q_OFF + Q_SIZE)
#define ENC_OFF  (P_OFF + 1)

#define LDB   72            // padded fp16 row: 144B (conflict-free ldmatrix)
#define LDBB  144
#define ESC   256.0f        // codebook pre-scale (exact power of 2)
#define NEG2S (-2.0f/256.0f)

// smem byte offsets
#define A_OFF    0                    // 1 image x 128 x 144 = 18432
#define B_OFF    18432                // 2 bufs x 4608
#define BCHUNKB  4608
#define XS_OFF   27648                // 128 x 64 f32 = 32768
#define E2_OFF   60416                // 1024 f32 = 4096
#define X2_OFF   64512                // 128 f32
#define RMIN_OFF 65024
#define RIDX_OFF 65536
#define B2_OFF   66048                // 128 f32 (second-best)
#define BND_OFF  66560                // 128 f32 (window)
#define LIST_OFF 67072                // 128 i32 (refine list)
#define CTR_OFF  67584                // 2 ints (sblk, nref)
#define SMEM_BYTES 67648

__device__ __half g_cbs[KCODE * LDB];  // hi image, scaled x256, padded
__device__ float  g_e2[KCODE];
__device__ int    g_ELbits, g_ENbits; // max residual / code norms (float bits, monotone)
__device__ int    g_counts[KCODE];    // zero at load; finalize re-zeroes
__device__ double g_loss_sum;
__device__ int    g_blk;              // work-steal counter; finalize re-zeroes

__device__ __forceinline__ uint32_t smem_u32(const void* p) {
    uint32_t a;
    asm("{ .reg .u64 t; cvta.to.shared.u64 t, %1; cvt.u32.u64 %0, t; }" : "=r"(a) : "l"(p));
    return a;
}
#define LDSM_X4(r0, r1, r2, r3, addr) \
    asm volatile("ldmatrix.sync.aligned.m8n8.x4.shared.b16 {%0,%1,%2,%3}, [%4];" \
                 : "=r"(r0), "=r"(r1), "=r"(r2), "=r"(r3) : "r"(addr))
#define MMA_F16(c0, c1, c2, c3, a0, a1, a2, a3, b0, b1) \
    asm volatile("mma.sync.aligned.m16n8k16.row.col.f32.f16.f16.f32 " \
                 "{%0,%1,%2,%3}, {%4,%5,%6,%7}, {%8,%9}, {%0,%1,%2,%3};" \
                 : "+f"(c0), "+f"(c1), "+f"(c2), "+f"(c3) \
                 : "r"(a0), "r"(a1), "r"(a2), "r"(a3), "r"(b0), "r"(b1))
#define CPA16(dst, src) \
    asm volatile("cp.async.cg.shared.global [%0], [%1], 16;" \
                 :: "r"((uint32_t)(dst)), "l"((unsigned long long)(src)) : "memory")
#define CPA_COMMIT() asm volatile("cp.async.commit_group;" ::: "memory")
#define CPA_WAIT0()  asm volatile("cp.async.wait_group 0;" ::: "memory")

// ---------------- prologue: hi fp16 image (x256) + e2 + max norms ----------------
__global__ void vq_prep_kernel(const float* __restrict__ cb) {
    int k = blockIdx.x * 128 + threadIdx.x;
    float e2 = 0.f, el2 = 0.f;
    for (int c = 0; c < DIMS; c++) {
        float v = cb[k * DIMS + c];
        e2 = fmaf(v, v, e2);
        float vs = v * ESC;
        __half h = __float2half_rn(vs);
        float r1 = vs - __half2float(h);   // FULL residual in scaled units
        el2 = fmaf(r1, r1, el2);
        g_cbs[k * LDB + c] = h;
    }
    g_e2[k] = e2;
    float eln = sqrtf(el2) * 1.02f;        // fudge for fp32 norm rounding
    float en  = sqrtf(e2) * 1.02f;
    atomicMax(&g_ELbits, __float_as_int(eln));   // positive floats: bits monotone
    atomicMax(&g_ENbits, __float_as_int(en));
}

// ---------------- main fused persistent kernel ----------------
__global__ __launch_bounds__(THREADS, 2)
void vq_main_kernel(const float* __restrict__ x,
                    const float* __restrict__ cb,
                    float* __restrict__ out) {
    extern __shared__ char smem[];
    const uint32_t su = smem_u32(smem);
    float* xsf   = (float*)(smem + XS_OFF);
    float* e2s   = (float*)(smem + E2_OFF);
    float* x2s   = (float*)(smem + X2_OFF);
    float* rmin  = (float*)(smem + RMIN_OFF);
    int*   ridx  = (int*)(smem + RIDX_OFF);
    float* b2s   = (float*)(smem + B2_OFF);
    float* bnds  = (float*)(smem + BND_OFF);
    int*   rlist = (int*)(smem + LIST_OFF);
    int*   sblk  = (int*)(smem + CTR_OFF);
    int*   nref  = (int*)(smem + CTR_OFF + 4);

    const int tid  = threadIdx.x;
    const int wid  = tid >> 5;
    const int lane = tid & 31;

    #pragma unroll
    for (int i = tid; i < KCODE; i += THREADS) e2s[i] = g_e2[i];
    const float EL = __int_as_float(g_ELbits);
    const float EN = __int_as_float(g_ENbits);

    // cp.async slot map: 288 x 16B lines/chunk; slot0 all threads, slot1 iff tid<32
    const unsigned long long gb = (unsigned long long)__cvta_generic_to_global(g_cbs);
    const bool has2 = (tid < 32);
    const uint32_t cpa_dst0 = (uint32_t)tid * 16;
    const uint32_t cpa_dst1 = (uint32_t)(tid + 256) * 16;

    // B x4 lane offset: mats {ks_lo:16B0, ks_lo:16B1, ks_hi:16B0, ks_hi:16B1}
    const int bofs4 = (lane & 7) * LDBB + ((lane >> 3) & 1) * 16 + (lane >> 4) * 32;
    const int r0 = wid * 16 + (lane >> 2);
    const int r1 = r0 + 8;

    while (true) {
        __syncthreads();
        if (tid == 0) { *sblk = atomicAdd(&g_blk, 1); *nref = 0; }
        __syncthreads();
        const int blk = *sblk;
        if (blk >= NBLK) break;

        const int n0  = blk * BM;
        const int b   = n0 >> 10;
        const int hw0 = n0 & 1023;
        const float* xb = x + (size_t)b * 65536 + hw0;

        // prefetch B chunk 0
        CPA16(su + B_OFF + cpa_dst0, gb + cpa_dst0);
        if (has2) CPA16(su + B_OFF + cpa_dst1, gb + cpa_dst1);
        CPA_COMMIT();

        // A setup: fp16 hi split + fp32 row cache + norms + window
        if (tid < BM) {
            int r = tid;
            float x2 = 0.f, xh2 = 0.f, xl2 = 0.f;
            #pragma unroll 8
            for (int c = 0; c < DIMS; c++) {
                float v = xb[c * 1024 + r];
                x2 = fmaf(v, v, x2);
                xsf[r * DIMS + c] = v;
                __half h = __float2half_rn(v);
                float hv = __half2float(h);
                float l = v - hv;
                xh2 = fmaf(hv, hv, xh2);
                xl2 = fmaf(l, l, xl2);
                *(__half*)(smem + A_OFF + r * LDBB + c * 2) = h;
            }
            x2s[r] = x2;
            float B = 2.f * (sqrtf(xh2) * EL * (1.0f / 256.0f) + sqrtf(xl2) * EN);
            bnds[r] = 1.25f * B + 5e-5f;     // safety margin + accum/combine slack
        }
        __syncthreads();

        // A fragments: 1 image x 4 k-steps
        uint32_t af[4][4];
        {
            int row = wid * 16 + (lane & 15);
            int kh  = (lane >> 4) & 1;
            #pragma unroll
            for (int ks = 0; ks < 4; ks++) {
                uint32_t a = su + A_OFF + row * LDBB + ks * 32 + kh * 16;
                LDSM_X4(af[ks][0], af[ks][1], af[ks][2], af[ks][3], a);
            }
        }

        const float x2_0 = x2s[r0], x2_1 = x2s[r1];
        float best0 = 3.4e38f, best1 = 3.4e38f;
        float scnd0 = 3.4e38f, scnd1 = 3.4e38f;
        int   bidx0 = 0,       bidx1 = 0;

        float* encb = out + ENC_OFF + (size_t)n0 * KCODE;
        float4* enc4 = (float4*)(encb + 2);
        if (tid == 0) *(float2*)encb = make_float2(0.f, 0.f);
        if (tid == 1) *(float2*)(encb + (size_t)BM * KCODE - 2) = make_float2(0.f, 0.f);

        for (int nt = 0; nt < NCHUNK; nt++) {
            CPA_WAIT0();
            __syncthreads();
            if (nt + 1 < NCHUNK) {
                uint32_t d0 = su + B_OFF + ((nt + 1) & 1) * BCHUNKB;
                unsigned long long so = gb + (unsigned long long)(nt + 1) * BCHUNKB;
                CPA16(d0 + cpa_dst0, so + cpa_dst0);
                if (has2) CPA16(d0 + cpa_dst1, so + cpa_dst1);
                CPA_COMMIT();
            }
            const uint32_t bufo = su + B_OFF + (nt & 1) * BCHUNKB;

            float acc[4][4];
            #pragma unroll
            for (int t = 0; t < 4; t++)
                #pragma unroll
                for (int j = 0; j < 4; j++) acc[t][j] = 0.f;

            #pragma unroll
            for (int kp = 0; kp < 2; kp++) {
                const int k0 = kp * 2, k1 = kp * 2 + 1;
                #pragma unroll
                for (int t = 0; t < 4; t++) {
                    uint32_t bh[4];
                    LDSM_X4(bh[0], bh[1], bh[2], bh[3],
                            bufo + t * 8 * LDBB + kp * 64 + bofs4);
                    MMA_F16(acc[t][0],acc[t][1],acc[t][2],acc[t][3],
                            af[k0][0],af[k0][1],af[k0][2],af[k0][3], bh[0],bh[1]);
                    MMA_F16(acc[t][0],acc[t][1],acc[t][2],acc[t][3],
                            af[k1][0],af[k1][1],af[k1][2],af[k1][3], bh[2],bh[3]);
                }
            }

            // fused distance + argmin with second-best tracking
            #pragma unroll
            for (int t = 0; t < 4; t++) {
                int c0 = nt * CHW + t * 8 + (lane & 3) * 2;
                float e2a = e2s[c0], e2b = e2s[c0 + 1];
                float d;
                d = fmaf(NEG2S, acc[t][0], x2_0) + e2a;
                if (d < best0) { scnd0 = best0; best0 = d; bidx0 = c0; }
                else scnd0 = fminf(scnd0, d);
                d = fmaf(NEG2S, acc[t][1], x2_0) + e2b;
                if (d < best0) { scnd0 = best0; best0 = d; bidx0 = c0 + 1; }
                else scnd0 = fminf(scnd0, d);
                d = fmaf(NEG2S, acc[t][2], x2_1) + e2a;
                if (d < best1) { scnd1 = best1; best1 = d; bidx1 = c0; }
                else scnd1 = fminf(scnd1, d);
                d = fmaf(NEG2S, acc[t][3], x2_1) + e2b;
                if (d < best1) { scnd1 = best1; best1 = d; bidx1 = c0 + 1; }
                else scnd1 = fminf(scnd1, d);
            }

            // interleaved encodings zero-fill
            #pragma unroll
            for (int u = 0; u < 4; u++) {
                int i = nt * 1024 + u * 256 + tid;
                if (i < 32767) enc4[i] = make_float4(0.f, 0.f, 0.f, 0.f);
            }
        }

        // cross-lane reduce of (best, second, idx); ties => window-flagged anyway
        #pragma unroll
        for (int off = 1; off < 4; off <<= 1) {
            float ob  = __shfl_xor_sync(0xffffffffu, best0, off);
            float ob2 = __shfl_xor_sync(0xffffffffu, scnd0, off);
            int   oi  = __shfl_xor_sync(0xffffffffu, bidx0, off);
            if (ob < best0) { scnd0 = fminf(best0, ob2); best0 = ob; bidx0 = oi; }
            else            { scnd0 = fminf(scnd0, fminf(ob, 3.4e38f)); scnd0 = fminf(scnd0, ob); }
            ob  = __shfl_xor_sync(0xffffffffu, best1, off);
            ob2 = __shfl_xor_sync(0xffffffffu, scnd1, off);
            oi  = __shfl_xor_sync(0xffffffffu, bidx1, off);
            if (ob < best1) { scnd1 = fminf(best1, ob2); best1 = ob; bidx1 = oi; }
            else            { scnd1 = fminf(scnd1, ob); }
        }
        if ((lane & 3) == 0) {
            rmin[r0] = best0; ridx[r0] = bidx0; b2s[r0] = scnd0;
            rmin[r1] = best1; ridx[r1] = bidx1; b2s[r1] = scnd1;
        }
        __syncthreads();

        // flag ambiguous rows (window contains possible exact-argmin change)
        if (tid < BM) {
            if (b2s[tid] - rmin[tid] <= bnds[tid]) {
                int p = atomicAdd(nref, 1);
                rlist[p] = tid;
            }
        }
        __syncthreads();

        // exact fp32 refinement: whole CTA per flagged row (4 codes/thread)
        const int nr = *nref;
        for (int q = 0; q < nr; q++) {
            const int rr = rlist[q];
            const float xr2 = x2s[rr];
            const float* xrow = &xsf[rr * DIMS];
            float bd = 3.4e38f;
            int   bk = 0x7fffffff;
            #pragma unroll
            for (int u = 0; u < 4; u++) {
                int k = tid + u * 256;          // ascending per thread
                float dot = 0.f;
                #pragma unroll
                for (int c = 0; c < DIMS; c++)
                    dot = fmaf(xrow[c], cb[k * DIMS + c], dot);
                float d = fmaf(-2.f, dot, xr2) + e2s[k];
                if (d < bd || (d == bd && k < bk)) { bd = d; bk = k; }
            }
            #pragma unroll
            for (int o = 16; o > 0; o >>= 1) {
                float od = __shfl_xor_sync(0xffffffffu, bd, o);
                int   ok = __shfl_xor_sync(0xffffffffu, bk, o);
                if (od < bd || (od == bd && ok < bk)) { bd = od; bk = ok; }
            }
            __syncthreads();
            if (lane == 0) { rmin[rr] = bd; ridx[rr] = bk; }  // all warps agree? no:
            __syncthreads();
            // cross-warp final: warp leaders' results are in rmin[rr] races — redo safely
            if (wid == 0) {
                // gather 8 warp minima via smem scratch in rlist[64+wid]? simpler:
            }
            // NOTE: cross-warp reduce done via shared scratch below
            if (lane == 0) { ((float*)(smem + B2_OFF))[64 + wid] = bd;
                             ((int*)(smem + BND_OFF))[64 + wid]  = bk; }
            __syncthreads();
            if (tid == 0) {
                float fb = 3.4e38f; int fk = 0x7fffffff;
                #pragma unroll
                for (int w = 0; w < 8; w++) {
                    float vv = ((float*)(smem + B2_OFF))[64 + w];
                    int   kk = ((int*)(smem + BND_OFF))[64 + w];
                    if (vv < fb || (vv == fb && kk < fk)) { fb = vv; fk = kk; }
                }
                rmin[rr] = fb; ridx[rr] = fk;
            }
            __syncthreads();
        }

        if (tid < BM) atomicAdd(&g_counts[ridx[tid]], 1);

        if (tid < 32) {
            double s = (double)rmin[tid] + (double)rmin[tid + 32]
                     + (double)rmin[tid + 64] + (double)rmin[tid + 96];
            #pragma unroll
            for (int o = 16; o > 0; o >>= 1)
                s += __shfl_down_sync(0xffffffffu, s, o);
            if (tid == 0) atomicAdd(&g_loss_sum, s);
        }

        // quantized output (NCHW), coalesced over r
        float* qout = out + Q_OFF;
        #pragma unroll
        for (int i = 0; i < (BM * DIMS) / THREADS; i++) {
            int idx = tid + i * THREADS;
            int c = idx >> 7;
            int r = idx & 127;
            qout[(size_t)b * 65536 + (size_t)c * 1024 + hw0 + r] =
                cb[(size_t)ridx[r] * DIMS + c];
        }

        if (tid < BM)
            encb[(size_t)tid * KCODE + ridx[tid]] = 1.0f;
    }
}

__global__ void vq_finalize_kernel(float* __restrict__ out) {
    __shared__ float red[8];
    int t = threadIdx.x;
    float acc = 0.f;
    #pragma unroll
    for (int i = 0; i < 4; i++) {
        int k = t + i * 256;
        int c = g_counts[k];
        g_counts[k] = 0;
        float p = (float)c * (1.f / 65536.f);
        acc += p * logf(p + 1e-10f);
    }
    #pragma unroll
    for (int o = 16; o > 0; o >>= 1)
        acc += __shfl_down_sync(0xffffffffu, acc, o);
    if ((t & 31) == 0) red[t >> 5] = acc;
    __syncthreads();
    if (t == 0) {
        float s = 0.f;
        #pragma unroll
        for (int w = 0; w < 8; w++) s += red[w];
        out[P_OFF] = expf(-s);
        out[0]     = (float)(1.25 * g_loss_sum / 4194304.0);
        g_loss_sum = 0.0;
        g_blk      = 0;
    }
}

__global__ void vq_nop_kernel() {}

extern "C" void kernel_launch(void* const* d_in, const int* in_sizes, int n_in,
                              void* d_out, int out_size) {
    const float* x  = (const float*)d_in[0];
    const float* cb = (const float*)d_in[1];
    float* out = (float*)d_out;

    cudaFuncSetAttribute(vq_main_kernel,
                         cudaFuncAttributeMaxDynamicSharedMemorySize, SMEM_BYTES);

    vq_prep_kernel<<<8, 128>>>(cb);
    vq_nop_kernel<<<1, 32>>>();
    vq_nop_kernel<<<1, 32>>>();
    vq_main_kernel<<<GRID, THREADS, SMEM_BYTES>>>(x, cb, out);
    vq_finalize_kernel<<<1, 256>>>(out);
}

// round 11
// speedup vs baseline: 1.8298x; 1.8298x over previous
#include <cuda_runtime.h>
#include <cuda_fp16.h>
#include <math.h>
#include <stdint.h>

#define NROWS 65536
#define DIMS  64
#define KCODE 1024
#define BM    128
#define THREADS 256
#define NCHUNK 32           // 32 chunks of 32 codes
#define CHW    32
#define NBLK   (NROWS/BM)   // 512 row-blocks
#define GRID   296          // 148 SMs x occ 2; work-stealing

// output layout (floats): [loss(1) | quantized(4194304) | perplexity(1) | encodings(67108864)]
#define Q_OFF    1
#define Q_SIZE   4194304
#define P_OFF    (Q_OFF + Q_SIZE)
#define ENC_OFF  (P_OFF + 1)

#define LDB   72            // padded fp16 row: 144B (conflict-free ldmatrix)
#define LDBB  144
#define ESC   256.0f        // codebook pre-scale (exact power of 2)
#define NEG2S (-2.0f/256.0f)
#define XSL   65            // fp32 x row pad (conflict-free both directions)

// smem byte offsets
#define A_OFF    0                    // 1 image x 128 x 144 = 18432
#define B_OFF    18432                // 2 bufs x 4608
#define BCHUNKB  4608
#define XS_OFF   27648                // 128 x 65 f32 = 33280
#define E2_OFF   60928                // 1024 f32 = 4096
#define X2_OFF   65024                // 128 f32
#define RMIN_OFF 65536
#define RIDX_OFF 66048
#define B2_OFF   66560                // 128 f32 (second-best)
#define BND_OFF  67072                // 128 f32 (window)
#define LIST_OFF 67584                // 128 i32 (refine list)
#define CTR_OFF  68096                // sblk, nref
#define SMEM_BYTES 68224

__device__ __half g_cbs[KCODE * LDB];     // hi image, scaled x256, padded
__device__ float  g_cbT[DIMS * KCODE];    // transposed fp32 codebook [c][k]
__device__ float  g_e2[KCODE];
__device__ int    g_ELbits, g_ENbits;     // max residual / code norms (monotone bits)
__device__ int    g_counts[KCODE];        // zero at load; finalize re-zeroes
__device__ double g_loss_sum;
__device__ int    g_blk;                  // work-steal counter; finalize re-zeroes

__device__ __forceinline__ uint32_t smem_u32(const void* p) {
    uint32_t a;
    asm("{ .reg .u64 t; cvta.to.shared.u64 t, %1; cvt.u32.u64 %0, t; }" : "=r"(a) : "l"(p));
    return a;
}
#define LDSM_X4(r0, r1, r2, r3, addr) \
    asm volatile("ldmatrix.sync.aligned.m8n8.x4.shared.b16 {%0,%1,%2,%3}, [%4];" \
                 : "=r"(r0), "=r"(r1), "=r"(r2), "=r"(r3) : "r"(addr))
#define MMA_F16(c0, c1, c2, c3, a0, a1, a2, a3, b0, b1) \
    asm volatile("mma.sync.aligned.m16n8k16.row.col.f32.f16.f16.f32 " \
                 "{%0,%1,%2,%3}, {%4,%5,%6,%7}, {%8,%9}, {%0,%1,%2,%3};" \
                 : "+f"(c0), "+f"(c1), "+f"(c2), "+f"(c3) \
                 : "r"(a0), "r"(a1), "r"(a2), "r"(a3), "r"(b0), "r"(b1))
#define CPA16(dst, src) \
    asm volatile("cp.async.cg.shared.global [%0], [%1], 16;" \
                 :: "r"((uint32_t)(dst)), "l"((unsigned long long)(src)) : "memory")
#define CPA_COMMIT() asm volatile("cp.async.commit_group;" ::: "memory")
#define CPA_WAIT0()  asm volatile("cp.async.wait_group 0;" ::: "memory")

// ---------------- prologue: hi fp16 image (x256) + fp32 transpose + e2 + norms ----------------
__global__ void vq_prep_kernel(const float* __restrict__ cb) {
    int k = blockIdx.x * 128 + threadIdx.x;
    float e2 = 0.f, el2 = 0.f;
    for (int c = 0; c < DIMS; c++) {
        float v = cb[k * DIMS + c];
        e2 = fmaf(v, v, e2);
        g_cbT[c * KCODE + k] = v;
        float vs = v * ESC;
        __half h = __float2half_rn(vs);
        float r1 = vs - __half2float(h);   // full residual (scaled units)
        el2 = fmaf(r1, r1, el2);
        g_cbs[k * LDB + c] = h;
    }
    g_e2[k] = e2;
    float eln = sqrtf(el2) * 1.02f;
    float en  = sqrtf(e2) * 1.02f;
    atomicMax(&g_ELbits, __float_as_int(eln));   // positive floats: bits monotone
    atomicMax(&g_ENbits, __float_as_int(en));
}

// ---------------- main fused persistent kernel ----------------
__global__ __launch_bounds__(THREADS, 2)
void vq_main_kernel(const float* __restrict__ x,
                    const float* __restrict__ cb,
                    float* __restrict__ out) {
    extern __shared__ char smem[];
    const uint32_t su = smem_u32(smem);
    float* xsf   = (float*)(smem + XS_OFF);
    float* e2s   = (float*)(smem + E2_OFF);
    float* x2s   = (float*)(smem + X2_OFF);
    float* rmin  = (float*)(smem + RMIN_OFF);
    int*   ridx  = (int*)(smem + RIDX_OFF);
    float* b2s   = (float*)(smem + B2_OFF);
    float* bnds  = (float*)(smem + BND_OFF);
    int*   rlist = (int*)(smem + LIST_OFF);
    int*   sblk  = (int*)(smem + CTR_OFF);
    int*   nref  = (int*)(smem + CTR_OFF + 4);

    const int tid  = threadIdx.x;
    const int wid  = tid >> 5;
    const int lane = tid & 31;

    #pragma unroll
    for (int i = tid; i < KCODE; i += THREADS) e2s[i] = g_e2[i];
    const float EL = __int_as_float(g_ELbits);
    const float EN = __int_as_float(g_ENbits);

    // cp.async slot map: 288 x 16B lines/chunk; slot0 all threads, slot1 iff tid<32
    const unsigned long long gb = (unsigned long long)__cvta_generic_to_global(g_cbs);
    const bool has2 = (tid < 32);
    const uint32_t cpa_dst0 = (uint32_t)tid * 16;
    const uint32_t cpa_dst1 = (uint32_t)(tid + 256) * 16;

    // B x4 lane offset: mats {ks_lo:16B0, ks_lo:16B1, ks_hi:16B0, ks_hi:16B1}
    const int bofs4 = (lane & 7) * LDBB + ((lane >> 3) & 1) * 16 + (lane >> 4) * 32;
    const int r0 = wid * 16 + (lane >> 2);
    const int r1 = r0 + 8;

    while (true) {
        __syncthreads();
        if (tid == 0) { *sblk = atomicAdd(&g_blk, 1); *nref = 0; }
        __syncthreads();
        const int blk = *sblk;
        if (blk >= NBLK) break;

        const int n0  = blk * BM;
        const int b   = n0 >> 10;
        const int hw0 = n0 & 1023;
        const float* xb = x + (size_t)b * 65536 + hw0;

        // prefetch B chunk 0
        CPA16(su + B_OFF + cpa_dst0, gb + cpa_dst0);
        if (has2) CPA16(su + B_OFF + cpa_dst1, gb + cpa_dst1);
        CPA_COMMIT();

        // A setup: fp16 hi split + fp32 row cache + norms + window
        if (tid < BM) {
            int r = tid;
            float x2 = 0.f, xh2 = 0.f, xl2 = 0.f;
            #pragma unroll 8
            for (int c = 0; c < DIMS; c++) {
                float v = xb[c * 1024 + r];
                x2 = fmaf(v, v, x2);
                xsf[r * XSL + c] = v;
                __half h = __float2half_rn(v);
                float hv = __half2float(h);
                float l = v - hv;
                xh2 = fmaf(hv, hv, xh2);
                xl2 = fmaf(l, l, xl2);
                *(__half*)(smem + A_OFF + r * LDBB + c * 2) = h;
            }
            x2s[r] = x2;
            // per-code distance error bound B; safe gap window = 2.05*B + slack
            float B = 2.f * (sqrtf(xh2) * EL * (1.0f / 256.0f) + sqrtf(xl2) * EN);
            bnds[r] = 2.05f * B + 1e-4f;
        }
        __syncthreads();

        // A fragments: 1 image x 4 k-steps
        uint32_t af[4][4];
        {
            int row = wid * 16 + (lane & 15);
            int kh  = (lane >> 4) & 1;
            #pragma unroll
            for (int ks = 0; ks < 4; ks++) {
                uint32_t a = su + A_OFF + row * LDBB + ks * 32 + kh * 16;
                LDSM_X4(af[ks][0], af[ks][1], af[ks][2], af[ks][3], a);
            }
        }

        const float x2_0 = x2s[r0], x2_1 = x2s[r1];
        float best0 = 3.4e38f, best1 = 3.4e38f;
        float scnd0 = 3.4e38f, scnd1 = 3.4e38f;
        int   bidx0 = -1,      bidx1 = -1;

        float* encb = out + ENC_OFF + (size_t)n0 * KCODE;
        float4* enc4 = (float4*)(encb + 2);
        if (tid == 0) *(float2*)encb = make_float2(0.f, 0.f);
        if (tid == 1) *(float2*)(encb + (size_t)BM * KCODE - 2) = make_float2(0.f, 0.f);

        for (int nt = 0; nt < NCHUNK; nt++) {
            CPA_WAIT0();
            __syncthreads();
            if (nt + 1 < NCHUNK) {
                uint32_t d0 = su + B_OFF + ((nt + 1) & 1) * BCHUNKB;
                unsigned long long so = gb + (unsigned long long)(nt + 1) * BCHUNKB;
                CPA16(d0 + cpa_dst0, so + cpa_dst0);
                if (has2) CPA16(d0 + cpa_dst1, so + cpa_dst1);
                CPA_COMMIT();
            }
            const uint32_t bufo = su + B_OFF + (nt & 1) * BCHUNKB;

            float acc[4][4];
            #pragma unroll
            for (int t = 0; t < 4; t++)
                #pragma unroll
                for (int j = 0; j < 4; j++) acc[t][j] = 0.f;

            #pragma unroll
            for (int kp = 0; kp < 2; kp++) {
                const int k0 = kp * 2, k1 = kp * 2 + 1;
                #pragma unroll
                for (int t = 0; t < 4; t++) {
                    uint32_t bh[4];
                    LDSM_X4(bh[0], bh[1], bh[2], bh[3],
                            bufo + t * 8 * LDBB + kp * 64 + bofs4);
                    MMA_F16(acc[t][0],acc[t][1],acc[t][2],acc[t][3],
                            af[k0][0],af[k0][1],af[k0][2],af[k0][3], bh[0],bh[1]);
                    MMA_F16(acc[t][0],acc[t][1],acc[t][2],acc[t][3],
                            af[k1][0],af[k1][1],af[k1][2],af[k1][3], bh[2],bh[3]);
                }
            }

            // fused distance + top-2 tracking (ascending order, strict <)
            #pragma unroll
            for (int t = 0; t < 4; t++) {
                int c0 = nt * CHW + t * 8 + (lane & 3) * 2;
                float e2a = e2s[c0], e2b = e2s[c0 + 1];
                float d;
                d = fmaf(NEG2S, acc[t][0], x2_0) + e2a;
                if (d < best0) { scnd0 = best0; best0 = d; bidx0 = c0; }
                else scnd0 = fminf(scnd0, d);
                d = fmaf(NEG2S, acc[t][1], x2_0) + e2b;
                if (d < best0) { scnd0 = best0; best0 = d; bidx0 = c0 + 1; }
                else scnd0 = fminf(scnd0, d);
                d = fmaf(NEG2S, acc[t][2], x2_1) + e2a;
                if (d < best1) { scnd1 = best1; best1 = d; bidx1 = c0; }
                else scnd1 = fminf(scnd1, d);
                d = fmaf(NEG2S, acc[t][3], x2_1) + e2b;
                if (d < best1) { scnd1 = best1; best1 = d; bidx1 = c0 + 1; }
                else scnd1 = fminf(scnd1, d);
            }

            // interleaved encodings zero-fill
            #pragma unroll
            for (int u = 0; u < 4; u++) {
                int i = nt * 1024 + u * 256 + tid;
                if (i < 32767) enc4[i] = make_float4(0.f, 0.f, 0.f, 0.f);
            }
        }

        // cross-lane top-2 merge with element dedupe (lanes cover disjoint codes,
        // but after round 1 partners share the best element — dedupe by index)
        #pragma unroll
        for (int off = 1; off < 4; off <<= 1) {
            float od1 = __shfl_xor_sync(0xffffffffu, best0, off);
            float od2 = __shfl_xor_sync(0xffffffffu, scnd0, off);
            int   oi1 = __shfl_xor_sync(0xffffffffu, bidx0, off);
            if (oi1 == bidx0) {
                scnd0 = fminf(scnd0, od2);
            } else if (od1 < best0 || (od1 == best0 && oi1 < bidx0)) {
                scnd0 = fminf(best0, od2); best0 = od1; bidx0 = oi1;
            } else {
                scnd0 = fminf(scnd0, od1);
            }
            od1 = __shfl_xor_sync(0xffffffffu, best1, off);
            od2 = __shfl_xor_sync(0xffffffffu, scnd1, off);
            oi1 = __shfl_xor_sync(0xffffffffu, bidx1, off);
            if (oi1 == bidx1) {
                scnd1 = fminf(scnd1, od2);
            } else if (od1 < best1 || (od1 == best1 && oi1 < bidx1)) {
                scnd1 = fminf(best1, od2); best1 = od1; bidx1 = oi1;
            } else {
                scnd1 = fminf(scnd1, od1);
            }
        }
        if ((lane & 3) == 0) {
            rmin[r0] = best0; ridx[r0] = bidx0; b2s[r0] = scnd0;
            rmin[r1] = best1; ridx[r1] = bidx1; b2s[r1] = scnd1;
        }
        __syncthreads();

        // flag ambiguous rows (gap within window)
        if (tid < BM) {
            if (b2s[tid] - rmin[tid] <= bnds[tid]) {
                int p = atomicAdd(nref, 1);
                rlist[p] = tid;
            }
        }
        __syncthreads();

        // exact fp32 refinement: warp-per-row, coalesced float4 over transposed cb
        {
            const int nr = *nref;
            const float4* cbT4 = (const float4*)g_cbT;   // [64][256] float4
            for (int q = wid; q < nr; q += 8) {
                const int rr = rlist[q];
                const float xr2 = x2s[rr];
                const float* xrow = &xsf[rr * XSL];
                float bd = 3.4e38f;
                int   bk = 0;
                for (int kb = 0; kb < 8; kb++) {          // 128 codes per batch
                    const int k4 = kb * 32 + lane;
                    float s0 = 0.f, s1 = 0.f, s2 = 0.f, s3 = 0.f;
                    #pragma unroll 16
                    for (int c = 0; c < DIMS; c++) {
                        float4 e4 = cbT4[c * 256 + k4];
                        float xv = xrow[c];
                        s0 = fmaf(xv, e4.x, s0);
                        s1 = fmaf(xv, e4.y, s1);
                        s2 = fmaf(xv, e4.z, s2);
                        s3 = fmaf(xv, e4.w, s3);
                    }
                    const int kbase = kb * 128 + lane * 4;
                    float dd;
                    dd = fmaf(-2.f, s0, xr2) + e2s[kbase + 0];
                    if (dd < bd) { bd = dd; bk = kbase; }
                    dd = fmaf(-2.f, s1, xr2) + e2s[kbase + 1];
                    if (dd < bd) { bd = dd; bk = kbase + 1; }
                    dd = fmaf(-2.f, s2, xr2) + e2s[kbase + 2];
                    if (dd < bd) { bd = dd; bk = kbase + 2; }
                    dd = fmaf(-2.f, s3, xr2) + e2s[kbase + 3];
                    if (dd < bd) { bd = dd; bk = kbase + 3; }
                }
                #pragma unroll
                for (int o = 16; o > 0; o >>= 1) {
                    float od = __shfl_xor_sync(0xffffffffu, bd, o);
                    int   ok = __shfl_xor_sync(0xffffffffu, bk, o);
                    if (od < bd || (od == bd && ok < bk)) { bd = od; bk = ok; }
                }
                if (lane == 0) { rmin[rr] = bd; ridx[rr] = bk; }
            }
        }
        __syncthreads();

        if (tid < BM) atomicAdd(&g_counts[ridx[tid]], 1);

        if (tid < 32) {
            double s = (double)rmin[tid] + (double)rmin[tid + 32]
                     + (double)rmin[tid + 64] + (double)rmin[tid + 96];
            #pragma unroll
            for (int o = 16; o > 0; o >>= 1)
                s += __shfl_down_sync(0xffffffffu, s, o);
            if (tid == 0) atomicAdd(&g_loss_sum, s);
        }

        // quantized output (NCHW), coalesced over r
        float* qout = out + Q_OFF;
        #pragma unroll
        for (int i = 0; i < (BM * DIMS) / THREADS; i++) {
            int idx = tid + i * THREADS;
            int c = idx >> 7;
            int r = idx & 127;
            qout[(size_t)b * 65536 + (size_t)c * 1024 + hw0 + r] =
                cb[(size_t)ridx[r] * DIMS + c];
        }

        if (tid < BM)
            encb[(size_t)tid * KCODE + ridx[tid]] = 1.0f;
    }
}

__global__ void vq_finalize_kernel(float* __restrict__ out) {
    __shared__ float red[8];
    int t = threadIdx.x;
    float acc = 0.f;
    #pragma unroll
    for (int i = 0; i < 4; i++) {
        int k = t + i * 256;
        int c = g_counts[k];
        g_counts[k] = 0;
        float p = (float)c * (1.f / 65536.f);
        acc += p * logf(p + 1e-10f);
    }
    #pragma unroll
    for (int o = 16; o > 0; o >>= 1)
        acc += __shfl_down_sync(0xffffffffu, acc, o);
    if ((t & 31) == 0) red[t >> 5] = acc;
    __syncthreads();
    if (t == 0) {
        float s = 0.f;
        #pragma unroll
        for (int w = 0; w < 8; w++) s += red[w];
        out[P_OFF] = expf(-s);
        out[0]     = (float)(1.25 * g_loss_sum / 4194304.0);
        g_loss_sum = 0.0;
        g_blk      = 0;
    }
}

__global__ void vq_nop_kernel() {}

extern "C" void kernel_launch(void* const* d_in, const int* in_sizes, int n_in,
                              void* d_out, int out_size) {
    const float* x  = (const float*)d_in[0];
    const float* cb = (const float*)d_in[1];
    float* out = (float*)d_out;

    cudaFuncSetAttribute(vq_main_kernel,
                         cudaFuncAttributeMaxDynamicSharedMemorySize, SMEM_BYTES);

    vq_prep_kernel<<<8, 128>>>(cb);
    vq_nop_kernel<<<1, 32>>>();
    vq_nop_kernel<<<1, 32>>>();
    vq_main_kernel<<<GRID, THREADS, SMEM_BYTES>>>(x, cb, out);
    vq_finalize_kernel<<<1, 256>>>(out);
}

// round 12
// speedup vs baseline: 2.3450x; 1.2815x over previous
#include <cuda_runtime.h>
#include <cuda_fp16.h>
#include <math.h>
#include <stdint.h>

#define NROWS 65536
#define DIMS  64
#define KCODE 1024
#define BM    128
#define THREADS 256
#define NCHUNK 32           // 32 chunks of 32 codes
#define CHW    32
#define NBLK   (NROWS/BM)   // 512 row-blocks
#define GRID   296          // all-resident (148 SMs x occ 2); work-stealing
#define NPREP  260          // 256 element-split CTAs + 4 e2 CTAs

// output layout (floats): [loss(1) | quantized(4194304) | perplexity(1) | encodings(67108864)]
#define Q_OFF    1
#define Q_SIZE   4194304
#define P_OFF    (Q_OFF + Q_SIZE)
#define ENC_OFF  (P_OFF + 1)

#define LDB   72            // padded fp16 row: 144B (conflict-free ldmatrix)
#define LDBB  144
#define IMGB  (KCODE * LDBB)
#define ESC   256.0f        // codebook pre-scale (exact power of 2)
#define NEG2S (-2.0f/256.0f)

// smem byte offsets (same as R9)
#define A_OFF    0                    // 2 images x 128 x 144 = 36864
#define B_OFF    36864                // 2 bufs x 9216
#define BCHUNKB  9216
#define E2_OFF   55296                // 1024 f32
#define X2_OFF   59392                // 128 f32 (also finalize scratch)
#define RMIN_OFF 59904
#define RIDX_OFF 60416
#define BLK_OFF  60928                // sblk | last-flag
#define SMEM_BYTES 61056

__device__ __half g_cbs[2 * KCODE * LDB];  // 2 padded split images (scaled x256)
__device__ float  g_e2[KCODE];
__device__ int    g_counts[KCODE];   // zero at load; finalize re-zeroes
__device__ double g_loss_sum;
__device__ int    g_blk;             // work-steal counter; finalize re-zeroes
__device__ int    g_prep_done;       // prep CTA counter; finalize re-zeroes
__device__ int    g_done;            // finished-CTA counter; finalize re-zeroes

__device__ __forceinline__ uint32_t smem_u32(const void* p) {
    uint32_t a;
    asm("{ .reg .u64 t; cvta.to.shared.u64 t, %1; cvt.u32.u64 %0, t; }" : "=r"(a) : "l"(p));
    return a;
}
#define LDSM_X4(r0, r1, r2, r3, addr) \
    asm volatile("ldmatrix.sync.aligned.m8n8.x4.shared.b16 {%0,%1,%2,%3}, [%4];" \
                 : "=r"(r0), "=r"(r1), "=r"(r2), "=r"(r3) : "r"(addr))
#define MMA_F16(c0, c1, c2, c3, a0, a1, a2, a3, b0, b1) \
    asm volatile("mma.sync.aligned.m16n8k16.row.col.f32.f16.f16.f32 " \
                 "{%0,%1,%2,%3}, {%4,%5,%6,%7}, {%8,%9}, {%0,%1,%2,%3};" \
                 : "+f"(c0), "+f"(c1), "+f"(c2), "+f"(c3) \
                 : "r"(a0), "r"(a1), "r"(a2), "r"(a3), "r"(b0), "r"(b1))
#define CPA16(dst, src) \
    asm volatile("cp.async.cg.shared.global [%0], [%1], 16;" \
                 :: "r"((uint32_t)(dst)), "l"((unsigned long long)(src)) : "memory")
#define CPA_COMMIT() asm volatile("cp.async.commit_group;" ::: "memory")
#define CPA_WAIT0()  asm volatile("cp.async.wait_group 0;" ::: "memory")

// ---------------- single fused persistent kernel ----------------
__global__ __launch_bounds__(THREADS, 2)
void vq_kernel(const float* __restrict__ x,
               const float* __restrict__ cb,
               float* __restrict__ out) {
    extern __shared__ char smem[];
    const uint32_t su = smem_u32(smem);
    float* e2s  = (float*)(smem + E2_OFF);
    float* x2s  = (float*)(smem + X2_OFF);
    float* rmin = (float*)(smem + RMIN_OFF);
    int*   ridx = (int*)(smem + RIDX_OFF);
    int*   sblk = (int*)(smem + BLK_OFF);
    int*   slast = (int*)(smem + BLK_OFF + 4);

    const int tid  = threadIdx.x;
    const int wid  = tid >> 5;
    const int lane = tid & 31;
    const int bid  = blockIdx.x;

    // ================= phase 0: distributed codebook prep =================
    if (bid < 256) {
        // element-wise split: one element per thread (coalesced LDG)
        int idx = bid * 256 + tid;          // [0, 65536)
        int k = idx >> 6, c = idx & 63;
        float v = cb[idx];
        float vs = v * ESC;
        __half h = __float2half_rn(vs);
        float r1 = vs - __half2float(h);
        __half l = __float2half_rn(r1);
        g_cbs[k * LDB + c] = h;
        g_cbs[KCODE * LDB + k * LDB + c] = l;
        __threadfence();
        __syncthreads();
        if (tid == 0) atomicAdd(&g_prep_done, 1);
    } else if (bid < NPREP) {
        int k = (bid - 256) * 256 + tid;    // one code per thread
        float e2 = 0.f;
        #pragma unroll 8
        for (int c = 0; c < DIMS; c++) {
            float v = cb[k * DIMS + c];
            e2 = fmaf(v, v, e2);
        }
        g_e2[k] = e2;
        __threadfence();
        __syncthreads();
        if (tid == 0) atomicAdd(&g_prep_done, 1);
    }
    // spin until codebook images + e2 are published (all 296 CTAs resident)
    if (tid == 0) {
        while (atomicAdd(&g_prep_done, 0) < NPREP) __nanosleep(64);
    }
    __syncthreads();
    __threadfence();

    #pragma unroll
    for (int i = tid; i < KCODE; i += THREADS) e2s[i] = g_e2[i];

    // cp.async slot map: 576 x 16B lines/chunk; slots 0,1 all threads, slot 2 iff tid<64
    const unsigned long long gb = (unsigned long long)__cvta_generic_to_global(g_cbs);
    unsigned long long cpa_src[3];
    uint32_t cpa_dst[3];
    const bool has3 = (tid < 64);
    #pragma unroll
    for (int u = 0; u < 3; u++) {
        int i = tid + u * 256;
        int q = i / 288, r = i % 288;
        cpa_dst[u] = (uint32_t)(q * 4608 + r * 16);
        cpa_src[u] = gb + (unsigned long long)q * IMGB + (unsigned long long)r * 16;
    }

    // B x4 lane offset: mats {ks_lo:16B0, ks_lo:16B1, ks_hi:16B0, ks_hi:16B1}
    const int bofs4 = (lane & 7) * LDBB + ((lane >> 3) & 1) * 16 + (lane >> 4) * 32;
    const int r0 = wid * 16 + (lane >> 2);
    const int r1 = r0 + 8;

    // ================= phase 1: persistent work-stealing main loop =================
    while (true) {
        __syncthreads();
        if (tid == 0) *sblk = atomicAdd(&g_blk, 1);
        __syncthreads();
        const int blk = *sblk;
        if (blk >= NBLK) break;

        const int n0  = blk * BM;
        const int b   = n0 >> 10;
        const int hw0 = n0 & 1023;
        const float* xb = x + (size_t)b * 65536 + hw0;

        // prefetch B chunk 0
        {
            uint32_t d0 = su + B_OFF;
            CPA16(d0 + cpa_dst[0], cpa_src[0]);
            CPA16(d0 + cpa_dst[1], cpa_src[1]);
            if (has3) CPA16(d0 + cpa_dst[2], cpa_src[2]);
            CPA_COMMIT();
        }

        // A setup: 2-way fp16 split, one row per thread
        if (tid < BM) {
            int r = tid;
            float x2 = 0.f;
            #pragma unroll 8
            for (int c = 0; c < DIMS; c++) {
                float v = xb[c * 1024 + r];
                x2 = fmaf(v, v, x2);
                __half h = __float2half_rn(v);
                float rr1 = v - __half2float(h);
                __half l = __float2half_rn(rr1);
                *(__half*)(smem + A_OFF + 0 * 18432 + r * LDBB + c * 2) = h;
                *(__half*)(smem + A_OFF + 1 * 18432 + r * LDBB + c * 2) = l;
            }
            x2s[r] = x2;
        }
        __syncthreads();

        // A fragments: 2 images x 4 k-steps
        uint32_t af[2][4][4];
        {
            int row = wid * 16 + (lane & 15);
            int kh  = (lane >> 4) & 1;
            #pragma unroll
            for (int q = 0; q < 2; q++)
                #pragma unroll
                for (int ks = 0; ks < 4; ks++) {
                    uint32_t a = su + A_OFF + q * 18432 + row * LDBB + ks * 32 + kh * 16;
                    LDSM_X4(af[q][ks][0], af[q][ks][1], af[q][ks][2], af[q][ks][3], a);
                }
        }

        const float x2_0 = x2s[r0], x2_1 = x2s[r1];
        float best0 = 3.4e38f, best1 = 3.4e38f;
        int   bidx0 = 0,       bidx1 = 0;

        float* encb = out + ENC_OFF + (size_t)n0 * KCODE;
        float4* enc4 = (float4*)(encb + 2);
        if (tid == 0) *(float2*)encb = make_float2(0.f, 0.f);
        if (tid == 1) *(float2*)(encb + (size_t)BM * KCODE - 2) = make_float2(0.f, 0.f);

        for (int nt = 0; nt < NCHUNK; nt++) {
            CPA_WAIT0();
            __syncthreads();
            if (nt + 1 < NCHUNK) {
                uint32_t d0 = su + B_OFF + ((nt + 1) & 1) * BCHUNKB;
                unsigned long long so = (unsigned long long)(nt + 1) * 4608;
                CPA16(d0 + cpa_dst[0], cpa_src[0] + so);
                CPA16(d0 + cpa_dst[1], cpa_src[1] + so);
                if (has3) CPA16(d0 + cpa_dst[2], cpa_src[2] + so);
                CPA_COMMIT();
            }
            const uint32_t bufo = su + B_OFF + (nt & 1) * BCHUNKB;

            float acc[4][4];
            #pragma unroll
            for (int t = 0; t < 4; t++)
                #pragma unroll
                for (int j = 0; j < 4; j++) acc[t][j] = 0.f;

            #pragma unroll
            for (int kp = 0; kp < 2; kp++) {        // ks pairs {0,1}, {2,3}
                const int k0 = kp * 2, k1 = kp * 2 + 1;
                #pragma unroll
                for (int t = 0; t < 4; t++) {
                    uint32_t bh[4], bl[4];
                    LDSM_X4(bh[0], bh[1], bh[2], bh[3],
                            bufo + 0 * 4608 + t * 8 * LDBB + kp * 64 + bofs4);
                    LDSM_X4(bl[0], bl[1], bl[2], bl[3],
                            bufo + 1 * 4608 + t * 8 * LDBB + kp * 64 + bofs4);
                    // ks lo: hh, hl, lh
                    MMA_F16(acc[t][0],acc[t][1],acc[t][2],acc[t][3],
                            af[0][k0][0],af[0][k0][1],af[0][k0][2],af[0][k0][3],
                            bh[0],bh[1]);
                    MMA_F16(acc[t][0],acc[t][1],acc[t][2],acc[t][3],
                            af[0][k0][0],af[0][k0][1],af[0][k0][2],af[0][k0][3],
                            bl[0],bl[1]);
                    MMA_F16(acc[t][0],acc[t][1],acc[t][2],acc[t][3],
                            af[1][k0][0],af[1][k0][1],af[1][k0][2],af[1][k0][3],
                            bh[0],bh[1]);
                    // ks hi
                    MMA_F16(acc[t][0],acc[t][1],acc[t][2],acc[t][3],
                            af[0][k1][0],af[0][k1][1],af[0][k1][2],af[0][k1][3],
                            bh[2],bh[3]);
                    MMA_F16(acc[t][0],acc[t][1],acc[t][2],acc[t][3],
                            af[0][k1][0],af[0][k1][1],af[0][k1][2],af[0][k1][3],
                            bl[2],bl[3]);
                    MMA_F16(acc[t][0],acc[t][1],acc[t][2],acc[t][3],
                            af[1][k1][0],af[1][k1][1],af[1][k1][2],af[1][k1][3],
                            bh[2],bh[3]);
                }
            }

            // fused distance + argmin (ascending order, strict <); dot = acc/256
            #pragma unroll
            for (int t = 0; t < 4; t++) {
                int c0 = nt * CHW + t * 8 + (lane & 3) * 2;
                float e2a = e2s[c0], e2b = e2s[c0 + 1];
                float d;
                d = fmaf(NEG2S, acc[t][0], x2_0) + e2a;
                if (d < best0) { best0 = d; bidx0 = c0; }
                d = fmaf(NEG2S, acc[t][1], x2_0) + e2b;
                if (d < best0) { best0 = d; bidx0 = c0 + 1; }
                d = fmaf(NEG2S, acc[t][2], x2_1) + e2a;
                if (d < best1) { best1 = d; bidx1 = c0; }
                d = fmaf(NEG2S, acc[t][3], x2_1) + e2b;
                if (d < best1) { best1 = d; bidx1 = c0 + 1; }
            }

            // interleaved encodings zero-fill
            #pragma unroll
            for (int u = 0; u < 4; u++) {
                int i = nt * 1024 + u * 256 + tid;
                if (i < 32767) enc4[i] = make_float4(0.f, 0.f, 0.f, 0.f);
            }
        }

        // cross-lane argmin reduce (4 lanes per row), idx tie-break
        #pragma unroll
        for (int off = 1; off < 4; off <<= 1) {
            float ob0 = __shfl_xor_sync(0xffffffffu, best0, off);
            int   oi0 = __shfl_xor_sync(0xffffffffu, bidx0, off);
            if (ob0 < best0 || (ob0 == best0 && oi0 < bidx0)) { best0 = ob0; bidx0 = oi0; }
            float ob1 = __shfl_xor_sync(0xffffffffu, best1, off);
            int   oi1 = __shfl_xor_sync(0xffffffffu, bidx1, off);
            if (ob1 < best1 || (ob1 == best1 && oi1 < bidx1)) { best1 = ob1; bidx1 = oi1; }
        }
        if ((lane & 3) == 0) {
            rmin[r0] = best0; ridx[r0] = bidx0;
            rmin[r1] = best1; ridx[r1] = bidx1;
        }
        __syncthreads();

        if (tid < BM) atomicAdd(&g_counts[ridx[tid]], 1);

        if (tid < 32) {
            double s = (double)rmin[tid] + (double)rmin[tid + 32]
                     + (double)rmin[tid + 64] + (double)rmin[tid + 96];
            #pragma unroll
            for (int o = 16; o > 0; o >>= 1)
                s += __shfl_down_sync(0xffffffffu, s, o);
            if (tid == 0) atomicAdd(&g_loss_sum, s);
        }

        // quantized output (NCHW), coalesced over r
        float* qout = out + Q_OFF;
        #pragma unroll
        for (int i = 0; i < (BM * DIMS) / THREADS; i++) {
            int idx = tid + i * THREADS;
            int c = idx >> 7;
            int r = idx & 127;
            qout[(size_t)b * 65536 + (size_t)c * 1024 + hw0 + r] =
                cb[(size_t)ridx[r] * DIMS + c];
        }

        if (tid < BM)
            encb[(size_t)tid * KCODE + ridx[tid]] = 1.0f;
    }

    // ================= phase 2: last CTA finalizes + resets state =================
    __threadfence();
    if (tid == 0) {
        int d = atomicAdd(&g_done, 1);
        *slast = (d == GRID - 1) ? 1 : 0;
    }
    __syncthreads();
    if (*slast) {
        __threadfence();
        float* red = x2s;               // reuse smem scratch
        float acc = 0.f;
        #pragma unroll
        for (int i = 0; i < 4; i++) {
            int k = tid + i * 256;
            int c = g_counts[k];
            g_counts[k] = 0;
            float p = (float)c * (1.f / 65536.f);
            acc += p * logf(p + 1e-10f);
        }
        #pragma unroll
        for (int o = 16; o > 0; o >>= 1)
            acc += __shfl_down_sync(0xffffffffu, acc, o);
        if (lane == 0) red[wid] = acc;
        __syncthreads();
        if (tid == 0) {
            float s = 0.f;
            #pragma unroll
            for (int w = 0; w < 8; w++) s += red[w];
            out[P_OFF] = expf(-s);
            out[0]     = (float)(1.25 * g_loss_sum / 4194304.0);
            g_loss_sum   = 0.0;          // reset all state for next replay
            g_blk        = 0;
            g_done       = 0;
            g_prep_done  = 0;
        }
    }
}

extern "C" void kernel_launch(void* const* d_in, const int* in_sizes, int n_in,
                              void* d_out, int out_size) {
    const float* x  = (const float*)d_in[0];
    const float* cb = (const float*)d_in[1];
    float* out = (float*)d_out;

    cudaFuncSetAttribute(vq_kernel,
                         cudaFuncAttributeMaxDynamicSharedMemorySize, SMEM_BYTES);

    vq_kernel<<<GRID, THREADS, SMEM_BYTES>>>(x, cb, out);
}